// round 6
// baseline (speedup 1.0000x reference)
#include <cuda_runtime.h>
#include <math_constants.h>

// GraphPoolMol: masked neighborhood max-pool over graph Laplacian sparsity.
// B=64, MAX_ATOM=128, N_FEAT=128.
// out[b,i,f] = max_{j: L[b,i,j]!=0, j<n, i<n} x[b,j,f]; 0 if i>=n.
// diag(L)=1 => for i<n the neighbor set always contains j=i (so the
// reference's "no neighbor" fallback never fires for valid rows, and padding
// gather slots with the self row never changes the max).
//
// Warp-per-row, zero smem, zero barriers, direct L1/L2-cached gather.

#define AT 128
#define NF 128
#define THREADS 256

__device__ __forceinline__ float4 fmax4(float4 a, float4 b) {
    return make_float4(fmaxf(a.x, b.x), fmaxf(a.y, b.y),
                       fmaxf(a.z, b.z), fmaxf(a.w, b.w));
}

__global__ __launch_bounds__(THREADS, 6)
void graph_pool_mol_kernel(const float* __restrict__ xg,
                           const float* __restrict__ Lg,
                           const int* __restrict__ mol_slice,
                           float* __restrict__ outg)
{
    const int gw   = (blockIdx.x * THREADS + threadIdx.x) >> 5; // global warp
    const int lane = threadIdx.x & 31;
    const int b    = gw >> 7;          // batch
    const int i    = gw & (AT - 1);    // row

    const int n = __ldg(mol_slice + 2 * b);      // mol_slice[b,0] = n_atoms

    float4* out4 = reinterpret_cast<float4*>(outg) + ((size_t)b * AT + i) * 32;

    if (i >= n) {                                 // whole warp: padded row
        out4[lane] = make_float4(0.f, 0.f, 0.f, 0.f);
        return;
    }

    // ---- Load L row (one coalesced float4 per lane), build mask -----------
    const float4 Lv = __ldg(reinterpret_cast<const float4*>(
                                Lg + ((size_t)b * AT + i) * AT) + lane);
    const int j0 = 4 * lane;
    // Word q holds columns j = 4*bit + q.
    unsigned m0 = __ballot_sync(0xffffffffu, (Lv.x != 0.0f) && (j0 + 0 < n));
    unsigned m1 = __ballot_sync(0xffffffffu, (Lv.y != 0.0f) && (j0 + 1 < n));
    unsigned m2 = __ballot_sync(0xffffffffu, (Lv.z != 0.0f) && (j0 + 2 < n));
    unsigned m3 = __ballot_sync(0xffffffffu, (Lv.w != 0.0f) && (j0 + 3 < n));

    const int kmax = max(max(__popc(m0), __popc(m1)),
                         max(__popc(m2), __popc(m3)));   // >=1 (diag)

    // ---- Gather: 4 independent load chains, branch-free body --------------
    const float4* xb = reinterpret_cast<const float4*>(xg + (size_t)b * AT * NF);
    const float4 ninf = make_float4(-CUDART_INF_F, -CUDART_INF_F,
                                    -CUDART_INF_F, -CUDART_INF_F);
    float4 a0 = ninf, a1 = ninf, a2 = ninf, a3 = ninf;

    for (int k = 0; k < kmax; ++k) {
        // Peel one bit from each word; empty word -> self row (value already
        // in the max set, harmless).
        const int jA = m0 ? 4 * (__ffs(m0) - 1) + 0 : i;  m0 &= m0 - 1;
        const int jB = m1 ? 4 * (__ffs(m1) - 1) + 1 : i;  m1 &= m1 - 1;
        const int jC = m2 ? 4 * (__ffs(m2) - 1) + 2 : i;  m2 &= m2 - 1;
        const int jD = m3 ? 4 * (__ffs(m3) - 1) + 3 : i;  m3 &= m3 - 1;
        const float4 vA = __ldg(xb + jA * 32 + lane);
        const float4 vB = __ldg(xb + jB * 32 + lane);
        const float4 vC = __ldg(xb + jC * 32 + lane);
        const float4 vD = __ldg(xb + jD * 32 + lane);
        a0 = fmax4(a0, vA);
        a1 = fmax4(a1, vB);
        a2 = fmax4(a2, vC);
        a3 = fmax4(a3, vD);
    }

    out4[lane] = fmax4(fmax4(a0, a1), fmax4(a2, a3));
}

extern "C" void kernel_launch(void* const* d_in, const int* in_sizes, int n_in,
                              void* d_out, int out_size)
{
    const float* node_features = (const float*)d_in[0];
    const float* laplacian     = (const float*)d_in[1];
    const int*   mol_slice     = (const int*)d_in[2];
    // d_in[3] = l_slice (unused)

    float* out = (float*)d_out;

    const int B = 64;
    const int total_warps = B * AT;               // 8192 warps, 1 per row
    const int blocks = total_warps / (THREADS / 32);
    graph_pool_mol_kernel<<<blocks, THREADS>>>(
        node_features, laplacian, mol_slice, out);
}